// round 14
// baseline (speedup 1.0000x reference)
#include <cuda_runtime.h>
#include <cuda_bf16.h>
#include <math.h>
#include <stdint.h>

// Problem constants (GraphEmbedderGATNE): N=200000, R=4, D=128, U=32, A=16, E=131072, K=10
#define N_ENT 200000
#define R_ 4
#define D_ 128
#define U_ 32
#define A_ 16
#define E_ 131072
#define K_ 10
#define ES_TOTAL (2 * E_)                 // 262144 edge-sides
#define WPB 28                            // warps per block
#define ES_PER_WARP 8
#define THREADS (WPB * 32)                // 896
#define TILE 224                          // edge-sides per block (14 x 16-row MMA tiles)
#define NBLOCKS ((ES_TOTAL + TILE - 1) / TILE)   // 1171

#define QPAD 132                          // q tile row stride (conflict-free A frags)
#define MPAD 136                          // M tile row stride (conflict-free B frags)

// Shared-memory layout (float offsets).
// Phase 1 uses: W | w | Q | UNION(per-warp scratch)
// Phase 2 uses: W | w | Q | UNION(M tile)   <- M loaded AFTER phase 1
#define SM_W 0                            // W transposed: [r*512 + a*32 + u], 2048
#define SM_w 2048                         // w: [r*16 + a], 64
#define SM_Q 2112                         // q tile [row*132 + k], 29568 (reused as epilogue)
#define SM_UNION (SM_Q + TILE * QPAD)     // 31680
#define UR_OFF 0                          // ur: [r*33 + u], 132
#define WR_OFF 132                        // wr: [u*18 + a], 576
#define WARP_SCR 708                      // 28 * 708 = 19824 >= 17408 (M tile size)
#define UNION_FLOATS 19824
#define SMEM_FLOATS (SM_UNION + UNION_FLOATS)     // 51504
#define SMEM_BYTES (SMEM_FLOATS * 4)              // 206016 bytes

// bf16 copy of u table: [N][128] bf16 = 51.2 MB -> fully L2-resident
__device__ __nv_bfloat16 g_ub[(size_t)N_ENT * D_];

__device__ __forceinline__ float tanh_fast(float x) {
    float y;
    asm("tanh.approx.f32 %0, %1;" : "=f"(y) : "f"(x));
    return y;
}

__device__ __forceinline__ float tf32r(float x) {
    uint32_t y;
    asm("cvt.rna.tf32.f32 %0, %1;" : "=r"(y) : "f"(x));
    return __uint_as_float(y);
}

__device__ __forceinline__ float4 add4(float4 a, float4 b) {
    return make_float4(a.x + b.x, a.y + b.y, a.z + b.z, a.w + b.w);
}

// unpack uint2 (4 bf16) -> float4
__device__ __forceinline__ float4 ub2f4(uint2 raw) {
    __nv_bfloat162 lo = *(__nv_bfloat162*)&raw.x;
    __nv_bfloat162 hi = *(__nv_bfloat162*)&raw.y;
    float2 f01 = __bfloat1622float2(lo);
    float2 f23 = __bfloat1622float2(hi);
    return make_float4(f01.x, f01.y, f23.x, f23.y);
}

#define MMA_TF32(c0, c1, c2, c3, a0, a1, a2, a3, b0, b1)                      \
    asm volatile("mma.sync.aligned.m16n8k8.row.col.f32.tf32.tf32.f32 "        \
                 "{%0,%1,%2,%3}, {%4,%5,%6,%7}, {%8,%9}, {%0,%1,%2,%3};"      \
                 : "+f"(c0), "+f"(c1), "+f"(c2), "+f"(c3)                     \
                 : "r"(__float_as_uint(a0)), "r"(__float_as_uint(a1)),        \
                   "r"(__float_as_uint(a2)), "r"(__float_as_uint(a3)),        \
                   "r"(__float_as_uint(b0)), "r"(__float_as_uint(b1)))

// ------------- conversion kernel: u (fp32) -> g_ub (bf16), streaming --------
__global__ void __launch_bounds__(512)
conv_u_kernel(const float* __restrict__ u)
{
    size_t i = (size_t)blockIdx.x * 512 + threadIdx.x;   // one uint4 (8 elems) each
    if (i < (size_t)N_ENT * D_ / 8) {
        float4 v0 = ((const float4*)u)[2 * i];
        float4 v1 = ((const float4*)u)[2 * i + 1];
        __nv_bfloat162 p0 = __floats2bfloat162_rn(v0.x, v0.y);
        __nv_bfloat162 p1 = __floats2bfloat162_rn(v0.z, v0.w);
        __nv_bfloat162 p2 = __floats2bfloat162_rn(v1.x, v1.y);
        __nv_bfloat162 p3 = __floats2bfloat162_rn(v1.z, v1.w);
        uint4 o;
        o.x = *(uint32_t*)&p0; o.y = *(uint32_t*)&p1;
        o.z = *(uint32_t*)&p2; o.w = *(uint32_t*)&p3;
        ((uint4*)g_ub)[i] = o;
    }
}
#define CONV_BLOCKS ((N_ENT * D_ / 8 + 511) / 512)   // 6250

__global__ void __launch_bounds__(THREADS, 1)
gatne_kernel(const int* __restrict__ edge_index,    // [2, E]
             const float* __restrict__ edge_attr,   // [E, R]
             const int* __restrict__ nidx,          // [2, E, K]
             const float* __restrict__ emb,         // [N, D]
             const float* __restrict__ Wt,          // [R, U, A]
             const float* __restrict__ wv,          // [R, A]
             const float* __restrict__ Mt,          // [R, U, D]
             float* __restrict__ out)               // [2, E, D]
{
    extern __shared__ float smem[];
    const int tid = threadIdx.x;

    // --- cooperative loads: W tables (M tile deferred until after phase 1) ---
    for (int i = tid; i < R_ * U_ * A_; i += THREADS) {
        int r = i >> 9, rem = i & 511, uu = rem >> 4, a = rem & 15;
        smem[SM_W + r * 512 + a * 32 + uu] = Wt[i];
    }
    if (tid < R_ * A_) smem[SM_w + tid] = wv[tid];
    __syncthreads();

    const int warp = tid >> 5, lane = tid & 31;
    float* q_s  = smem + SM_Q;
    float* ur_s = smem + SM_UNION + warp * WARP_SCR + UR_OFF;
    float* wr_s = smem + SM_UNION + warp * WARP_SCR + WR_OFF;
    const float* W_s = smem + SM_W;
    const float* w_s = smem + SM_w;

    const int es_blk = blockIdx.x * TILE;
    const int rg = lane >> 3;
    const int cg = lane & 7;
    const int a0i = 2 * cg;

    // ========== Phase 1: attention -> q, pipelined bf16 gathers ===============
    {
        const int es0 = es_blk + warp * ES_PER_WARP;
        const uint2* ub = (const uint2*)g_ub;    // row = 32 uint2 (128 bf16)
        uint2 t[10];
        // prologue: indices + gathers for b=0 (clamped; tail block reads dummy)
        {
            long esc = (es0 < ES_TOTAL) ? es0 : (ES_TOTAL - 1);
            int my_n = (lane < K_) ? __ldg(nidx + esc * K_ + lane) : 0;
            #pragma unroll
            for (int k = 0; k < K_; ++k) {
                int nbr = __shfl_sync(0xffffffffu, my_n, k);
                t[k] = __ldg(&ub[(long)nbr * 32 + lane]);
            }
        }

        #pragma unroll 1
        for (int b = 0; b < ES_PER_WARP; ++b) {
            const int row = warp * ES_PER_WARP + b;
            const int es = es0 + b;
            const int e = es & (E_ - 1);
            const float4 ea = ((const float4*)edge_attr)[e];

            // prefetch neighbor indices for b+1 (long-latency, overlaps below)
            int my_n_next = 0;
            if (b + 1 < ES_PER_WARP) {
                long esn = (es + 1 < ES_TOTAL) ? (long)(es + 1) : (ES_TOTAL - 1);
                my_n_next = (lane < K_) ? __ldg(nidx + esn * K_ + lane) : 0;
            }

            // consume staged gathers for b: unpack + pairwise tree sum
            float4 f0 = add4(ub2f4(t[0]), ub2f4(t[1]));
            float4 f1 = add4(ub2f4(t[2]), ub2f4(t[3]));
            float4 f2 = add4(ub2f4(t[4]), ub2f4(t[5]));
            float4 f3 = add4(ub2f4(t[6]), ub2f4(t[7]));
            float4 f4 = add4(ub2f4(t[8]), ub2f4(t[9]));
            float4 au = add4(add4(add4(f0, f1), add4(f2, f3)), f4);
            const float ik = 1.0f / (float)K_;
            au.x *= ik; au.y *= ik; au.z *= ik; au.w *= ik;

            // issue gathers for b+1 NOW — overlap with the rest of this iteration
            if (b + 1 < ES_PER_WARP) {
                #pragma unroll
                for (int k = 0; k < K_; ++k) {
                    int nbr = __shfl_sync(0xffffffffu, my_n_next, k);
                    t[k] = __ldg(&ub[(long)nbr * 32 + lane]);
                }
            }

            // stash u_r to smem: layout [r*33 + u] (conflict-free)
            const int ub4 = 4 * cg;  // flat f = 4*lane+j -> r = lane>>3, u = 4*(lane&7)+j
            ur_s[rg * 33 + ub4 + 0] = au.x;
            ur_s[rg * 33 + ub4 + 1] = au.y;
            ur_s[rg * 33 + ub4 + 2] = au.z;
            ur_s[rg * 33 + ub4 + 3] = au.w;

            // W_r[u=lane][a] = sum_r ea[r] * W[r][u][a]  (W_s transposed [r][a][u])
            #pragma unroll
            for (int a2 = 0; a2 < 8; ++a2) {
                int a = 2 * a2;
                float g0 = fmaf(ea.x, W_s[a * 32 + lane],
                           fmaf(ea.y, W_s[512 + a * 32 + lane],
                           fmaf(ea.z, W_s[1024 + a * 32 + lane],
                                ea.w * W_s[1536 + a * 32 + lane])));
                float g1 = fmaf(ea.x, W_s[(a + 1) * 32 + lane],
                           fmaf(ea.y, W_s[512 + (a + 1) * 32 + lane],
                           fmaf(ea.z, W_s[1024 + (a + 1) * 32 + lane],
                                ea.w * W_s[1536 + (a + 1) * 32 + lane])));
                ((float2*)(wr_s + lane * 18))[a2] = make_float2(g0, g1);
            }
            __syncwarp();

            float t0 = 0.f, t1 = 0.f;
            #pragma unroll
            for (int uu = 0; uu < U_; ++uu) {
                float urv = ur_s[rg * 33 + uu];
                float2 w2 = *(const float2*)(wr_s + uu * 18 + a0i);
                t0 = fmaf(urv, w2.x, t0);
                t1 = fmaf(urv, w2.y, t1);
            }
            float wr0 = fmaf(ea.x, w_s[a0i], fmaf(ea.y, w_s[16 + a0i],
                        fmaf(ea.z, w_s[32 + a0i], ea.w * w_s[48 + a0i])));
            float wr1 = fmaf(ea.x, w_s[a0i + 1], fmaf(ea.y, w_s[16 + a0i + 1],
                        fmaf(ea.z, w_s[32 + a0i + 1], ea.w * w_s[48 + a0i + 1])));
            float sc = tanh_fast(t0) * wr0 + tanh_fast(t1) * wr1;

            sc += __shfl_xor_sync(0xffffffffu, sc, 1);
            sc += __shfl_xor_sync(0xffffffffu, sc, 2);
            sc += __shfl_xor_sync(0xffffffffu, sc, 4);
            float mx = sc;
            mx = fmaxf(mx, __shfl_xor_sync(0xffffffffu, mx, 8));
            mx = fmaxf(mx, __shfl_xor_sync(0xffffffffu, mx, 16));
            float ex = __expf(sc - mx);
            float ssum = ex;
            ssum += __shfl_xor_sync(0xffffffffu, ssum, 8);
            ssum += __shfl_xor_sync(0xffffffffu, ssum, 16);
            float att = __fdividef(ex, ssum);
            float av0 = __shfl_sync(0xffffffffu, att, 0);
            float av1 = __shfl_sync(0xffffffffu, att, 8);
            float av2 = __shfl_sync(0xffffffffu, att, 16);
            float av3 = __shfl_sync(0xffffffffu, att, 24);

            float vv = fmaf(av0, ur_s[0 * 33 + lane],
                       fmaf(av1, ur_s[1 * 33 + lane],
                       fmaf(av2, ur_s[2 * 33 + lane],
                            av3 * ur_s[3 * 33 + lane])));

            // q[row][r*32+lane] = tf32(ea[r]*vv)
            q_s[row * QPAD +      lane] = tf32r(ea.x * vv);
            q_s[row * QPAD + 32 + lane] = tf32r(ea.y * vv);
            q_s[row * QPAD + 64 + lane] = tf32r(ea.z * vv);
            q_s[row * QPAD + 96 + lane] = tf32r(ea.w * vv);
            __syncwarp();
        }
    }
    __syncthreads();

    // --- NOW load M tile (tf32-rounded) into the union region (over scratch) --
    for (int i = tid; i < D_ * D_; i += THREADS) {        // i = k*128 + d
        int k = i >> 7, d = i & 127;
        smem[SM_UNION + k * MPAD + d] = tf32r(__ldg(Mt + i));
    }
    __syncthreads();

    // ================= Phase 2: D[224x128] = q @ M via tf32 mma.sync ==========
    {
        const int rt = warp % 14;          // 14 row-tiles x 16 rows = 224
        const int h  = warp / 14;          // 2 d-halves x 64 cols
        const int gid = lane >> 2, tig = lane & 3;
        const float* Ms = smem + SM_UNION;

        float c[8][4];
        #pragma unroll
        for (int nt = 0; nt < 8; ++nt)
            c[nt][0] = c[nt][1] = c[nt][2] = c[nt][3] = 0.f;

        #pragma unroll 1
        for (int ks = 0; ks < 16; ++ks) {
            const int k0 = ks * 8;
            const int ar0 = (rt * 16 + gid) * QPAD + k0 + tig;
            const int ar1 = ar0 + 8 * QPAD;
            float a0 = q_s[ar0], a1 = q_s[ar1];
            float a2 = q_s[ar0 + 4], a3 = q_s[ar1 + 4];
            #pragma unroll
            for (int nt = 0; nt < 8; ++nt) {
                const int n0 = h * 64 + nt * 8 + gid;
                float b0 = Ms[(k0 + tig) * MPAD + n0];
                float b1 = Ms[(k0 + tig + 4) * MPAD + n0];
                MMA_TF32(c[nt][0], c[nt][1], c[nt][2], c[nt][3],
                         a0, a1, a2, a3, b0, b1);
            }
        }
        __syncthreads();   // all warps done reading q tile

        // fragments -> epilogue buffer (reuse q tile)
        float* epi = smem + SM_Q;
        #pragma unroll
        for (int nt = 0; nt < 8; ++nt) {
            const int col = h * 64 + nt * 8 + 2 * tig;
            const int row0 = rt * 16 + gid;
            *(float2*)(epi + row0 * QPAD + col)       = make_float2(c[nt][0], c[nt][1]);
            *(float2*)(epi + (row0 + 8) * QPAD + col) = make_float2(c[nt][2], c[nt][3]);
        }
    }
    __syncthreads();

    // ================= Epilogue: + emb gather, l2-normalize, store ============
    {
        const float* epi = smem + SM_Q;
        int ents[8];
        #pragma unroll
        for (int i = 0; i < 8; ++i) {
            int es = es_blk + warp * 8 + i;
            ents[i] = (es < ES_TOTAL) ? __ldg(edge_index + es) : 0;
        }
        #pragma unroll 1
        for (int i = 0; i < 8; ++i) {
            const int row = warp * 8 + i;
            const int es = es_blk + row;
            float4 bv = __ldcs(&((const float4*)emb)[(long)ents[i] * 32 + lane]);
            float4 cv = *(const float4*)(epi + row * QPAD + lane * 4);
            float v0 = cv.x + bv.x, v1 = cv.y + bv.y;
            float v2 = cv.z + bv.z, v3 = cv.w + bv.w;
            float ss = v0 * v0 + v1 * v1 + v2 * v2 + v3 * v3;
            ss += __shfl_xor_sync(0xffffffffu, ss, 1);
            ss += __shfl_xor_sync(0xffffffffu, ss, 2);
            ss += __shfl_xor_sync(0xffffffffu, ss, 4);
            ss += __shfl_xor_sync(0xffffffffu, ss, 8);
            ss += __shfl_xor_sync(0xffffffffu, ss, 16);
            float inv = 1.0f / fmaxf(sqrtf(ss), 1e-12f);
            float4 o = make_float4(v0 * inv, v1 * inv, v2 * inv, v3 * inv);
            if (es < ES_TOTAL)
                __stcs(&((float4*)out)[(long)es * 32 + lane], o);  // evict-first
        }
    }
}

extern "C" void kernel_launch(void* const* d_in, const int* in_sizes, int n_in,
                              void* d_out, int out_size)
{
    (void)in_sizes; (void)n_in; (void)out_size;
    const int*   edge_index = (const int*)d_in[0];
    const float* edge_attr  = (const float*)d_in[1];
    const int*   nidx       = (const int*)d_in[2];
    const float* emb        = (const float*)d_in[3];
    const float* utab       = (const float*)d_in[4];
    const float* Wt         = (const float*)d_in[5];
    const float* wv         = (const float*)d_in[6];
    const float* Mt         = (const float*)d_in[7];
    float* out = (float*)d_out;

    conv_u_kernel<<<CONV_BLOCKS, 512>>>(utab);

    cudaFuncSetAttribute(gatne_kernel,
                         cudaFuncAttributeMaxDynamicSharedMemorySize, SMEM_BYTES);
    gatne_kernel<<<NBLOCKS, THREADS, SMEM_BYTES>>>(
        edge_index, edge_attr, nidx, emb, Wt, wv, Mt, out);
}

// round 15
// speedup vs baseline: 1.0714x; 1.0714x over previous
#include <cuda_runtime.h>
#include <cuda_bf16.h>
#include <math.h>
#include <stdint.h>

// Problem constants (GraphEmbedderGATNE): N=200000, R=4, D=128, U=32, A=16, E=131072, K=10
#define N_ENT 200000
#define R_ 4
#define D_ 128
#define U_ 32
#define A_ 16
#define E_ 131072
#define K_ 10
#define ES_TOTAL (2 * E_)                 // 262144 edge-sides
#define WPB 24                            // warps per block
#define THREADS (WPB * 32)                // 768
#define TILE 192                          // rows per block = 96 edges x 2 sides
#define EDGES_PB (TILE / 2)               // 96 edges per block
#define NBLOCKS ((E_ + EDGES_PB - 1) / EDGES_PB)   // 1366

#define QPAD 132                          // q tile row stride (conflict-free A frags)
#define MPAD 136                          // M tile row stride (conflict-free B frags)

// Shared-memory layout (float offsets).
// Phase 1 uses: W4 | w | Q | UNION(per-warp scratch)
// Phase 2 uses: W4 | w | Q | UNION(M tile)   <- M loaded AFTER phase 1
#define SM_W 0                            // W repacked: [(a*32+u)*4 + r] float4-by-r, 2048
#define SM_w 2048                         // w: [r*16 + a], 64
#define SM_Q 2112                         // q tile [row*132 + k], 25344 (reused as epilogue)
#define SM_UNION (SM_Q + TILE * QPAD)     // 27456
#define UR_OFF 0                          // ur: [r*33 + u], 132
#define WR_OFF 132                        // wr: [u*18 + a], 576
#define WARP_SCR 708                      // 24*708 = 16992 <= 17408 (M tile)
#define SMEM_FLOATS (SM_UNION + D_ * MPAD)        // 44864
#define SMEM_BYTES (SMEM_FLOATS * 4)              // 179456 bytes

// bf16 copy of u table: [N][128] bf16 = 51.2 MB -> fully L2-resident
__device__ __nv_bfloat16 g_ub[(size_t)N_ENT * D_];

__device__ __forceinline__ float tanh_fast(float x) {
    float y;
    asm("tanh.approx.f32 %0, %1;" : "=f"(y) : "f"(x));
    return y;
}

__device__ __forceinline__ float tf32r(float x) {
    uint32_t y;
    asm("cvt.rna.tf32.f32 %0, %1;" : "=r"(y) : "f"(x));
    return __uint_as_float(y);
}

__device__ __forceinline__ float4 add4(float4 a, float4 b) {
    return make_float4(a.x + b.x, a.y + b.y, a.z + b.z, a.w + b.w);
}

// unpack uint2 (4 bf16) -> float4
__device__ __forceinline__ float4 ub2f4(uint2 raw) {
    __nv_bfloat162 lo = *(__nv_bfloat162*)&raw.x;
    __nv_bfloat162 hi = *(__nv_bfloat162*)&raw.y;
    float2 f01 = __bfloat1622float2(lo);
    float2 f23 = __bfloat1622float2(hi);
    return make_float4(f01.x, f01.y, f23.x, f23.y);
}

#define MMA_TF32(c0, c1, c2, c3, a0, a1, a2, a3, b0, b1)                      \
    asm volatile("mma.sync.aligned.m16n8k8.row.col.f32.tf32.tf32.f32 "        \
                 "{%0,%1,%2,%3}, {%4,%5,%6,%7}, {%8,%9}, {%0,%1,%2,%3};"      \
                 : "+f"(c0), "+f"(c1), "+f"(c2), "+f"(c3)                     \
                 : "r"(__float_as_uint(a0)), "r"(__float_as_uint(a1)),        \
                   "r"(__float_as_uint(a2)), "r"(__float_as_uint(a3)),        \
                   "r"(__float_as_uint(b0)), "r"(__float_as_uint(b1)))

// ------------- conversion kernel: u (fp32) -> g_ub (bf16), streaming --------
__global__ void __launch_bounds__(512)
conv_u_kernel(const float* __restrict__ u)
{
    size_t i = (size_t)blockIdx.x * 512 + threadIdx.x;   // one uint4 (8 elems) each
    if (i < (size_t)N_ENT * D_ / 8) {
        float4 v0 = ((const float4*)u)[2 * i];
        float4 v1 = ((const float4*)u)[2 * i + 1];
        __nv_bfloat162 p0 = __floats2bfloat162_rn(v0.x, v0.y);
        __nv_bfloat162 p1 = __floats2bfloat162_rn(v0.z, v0.w);
        __nv_bfloat162 p2 = __floats2bfloat162_rn(v1.x, v1.y);
        __nv_bfloat162 p3 = __floats2bfloat162_rn(v1.z, v1.w);
        uint4 o;
        o.x = *(uint32_t*)&p0; o.y = *(uint32_t*)&p1;
        o.z = *(uint32_t*)&p2; o.w = *(uint32_t*)&p3;
        ((uint4*)g_ub)[i] = o;
    }
}
#define CONV_BLOCKS ((N_ENT * D_ / 8 + 511) / 512)   // 6250

__global__ void __launch_bounds__(THREADS, 1)
gatne_kernel(const int* __restrict__ edge_index,    // [2, E]
             const float* __restrict__ edge_attr,   // [E, R]
             const int* __restrict__ nidx,          // [2, E, K]
             const float* __restrict__ emb,         // [N, D]
             const float* __restrict__ Wt,          // [R, U, A]
             const float* __restrict__ wv,          // [R, A]
             const float* __restrict__ Mt,          // [R, U, D]
             float* __restrict__ out)               // [2, E, D]
{
    extern __shared__ float smem[];
    const int tid = threadIdx.x;

    // --- cooperative loads: W repacked by-r into float4 (M tile deferred) ---
    for (int i = tid; i < R_ * U_ * A_; i += THREADS) {
        int r = i >> 9, rem = i & 511, uu = rem >> 4, a = rem & 15;
        smem[SM_W + (a * 32 + uu) * 4 + r] = Wt[i];
    }
    if (tid < R_ * A_) smem[SM_w + tid] = wv[tid];
    __syncthreads();

    const int warp = tid >> 5, lane = tid & 31;
    float* q_s  = smem + SM_Q;
    float* ur_s = smem + SM_UNION + warp * WARP_SCR + UR_OFF;
    float* wr_s = smem + SM_UNION + warp * WARP_SCR + WR_OFF;
    const float4* W_s4 = (const float4*)(smem + SM_W);
    const float* w_s = smem + SM_w;

    const int e0 = blockIdx.x * EDGES_PB;
    const int rg = lane >> 3;
    const int cg = lane & 7;
    const int a0i = 2 * cg;

    // ========== Phase 1: 4 edges x 2 sides per warp, W_r shared per edge ======
    {
        const int e_base = e0 + warp * 4;
        const uint2* ub = (const uint2*)g_ub;    // row = 32 uint2 (128 bf16)
        uint2 t[10];
        // prologue: stage unit 0 (j=0, side=0)
        {
            int e = e_base; if (e >= E_) e = E_ - 1;
            int my_n = (lane < K_) ? __ldg(nidx + (long)e * K_ + lane) : 0;
            #pragma unroll
            for (int k = 0; k < K_; ++k) {
                int nbr = __shfl_sync(0xffffffffu, my_n, k);
                t[k] = __ldg(&ub[(long)nbr * 32 + lane]);
            }
        }

        float4 ea = make_float4(0.f, 0.f, 0.f, 0.f);
        float wr0 = 0.f, wr1 = 0.f;

        #pragma unroll 1
        for (int u = 0; u < 8; ++u) {
            const int j = u >> 1, side = u & 1;
            int e = e_base + j; if (e >= E_) e = E_ - 1;
            const int row = side * EDGES_PB + warp * 4 + j;

            // prefetch next unit's neighbor indices (long-latency, overlaps below)
            int my_n_next = 0;
            if (u + 1 < 8) {
                int jn = (u + 1) >> 1, sn = (u + 1) & 1;
                int en = e_base + jn; if (en >= E_) en = E_ - 1;
                long esn = (long)sn * E_ + en;
                my_n_next = (lane < K_) ? __ldg(nidx + esn * K_ + lane) : 0;
            }

            // consume staged gathers: unpack + pairwise tree sum
            float4 f0 = add4(ub2f4(t[0]), ub2f4(t[1]));
            float4 f1 = add4(ub2f4(t[2]), ub2f4(t[3]));
            float4 f2 = add4(ub2f4(t[4]), ub2f4(t[5]));
            float4 f3 = add4(ub2f4(t[6]), ub2f4(t[7]));
            float4 f4 = add4(ub2f4(t[8]), ub2f4(t[9]));
            float4 au = add4(add4(add4(f0, f1), add4(f2, f3)), f4);
            const float ik = 1.0f / (float)K_;
            au.x *= ik; au.y *= ik; au.z *= ik; au.w *= ik;

            // issue gathers for next unit NOW — overlap with the rest
            if (u + 1 < 8) {
                #pragma unroll
                for (int k = 0; k < K_; ++k) {
                    int nbr = __shfl_sync(0xffffffffu, my_n_next, k);
                    t[k] = __ldg(&ub[(long)nbr * 32 + lane]);
                }
            }

            // stash u_r to smem: layout [r*33 + u] (conflict-free)
            const int ub4 = 4 * cg;  // flat f = 4*lane+jj -> r = lane>>3, u = 4*(lane&7)+jj
            ur_s[rg * 33 + ub4 + 0] = au.x;
            ur_s[rg * 33 + ub4 + 1] = au.y;
            ur_s[rg * 33 + ub4 + 2] = au.z;
            ur_s[rg * 33 + ub4 + 3] = au.w;

            if (side == 0) {
                // per-edge work, shared by both sides
                ea = ((const float4*)edge_attr)[e];
                // W_r[u=lane][a] = ea . W4[a][lane]  (one LDS.128 per a)
                #pragma unroll
                for (int a2 = 0; a2 < 8; ++a2) {
                    int a = 2 * a2;
                    float4 wA = W_s4[a * 32 + lane];
                    float4 wB = W_s4[(a + 1) * 32 + lane];
                    float g0 = fmaf(ea.x, wA.x, fmaf(ea.y, wA.y,
                               fmaf(ea.z, wA.z, ea.w * wA.w)));
                    float g1 = fmaf(ea.x, wB.x, fmaf(ea.y, wB.y,
                               fmaf(ea.z, wB.z, ea.w * wB.w)));
                    ((float2*)(wr_s + lane * 18))[a2] = make_float2(g0, g1);
                }
                // w_r[a] = ea . w[:, a]
                wr0 = fmaf(ea.x, w_s[a0i], fmaf(ea.y, w_s[16 + a0i],
                      fmaf(ea.z, w_s[32 + a0i], ea.w * w_s[48 + a0i])));
                wr1 = fmaf(ea.x, w_s[a0i + 1], fmaf(ea.y, w_s[16 + a0i + 1],
                      fmaf(ea.z, w_s[32 + a0i + 1], ea.w * w_s[48 + a0i + 1])));
            }
            __syncwarp();

            // t[r=rg][a0], t[r=rg][a0+1] = sum_u u_r[r][u] * W_r[u][a]
            float t0 = 0.f, t1 = 0.f;
            #pragma unroll
            for (int uu = 0; uu < U_; ++uu) {
                float urv = ur_s[rg * 33 + uu];
                float2 w2 = *(const float2*)(wr_s + uu * 18 + a0i);
                t0 = fmaf(urv, w2.x, t0);
                t1 = fmaf(urv, w2.y, t1);
            }
            float sc = tanh_fast(t0) * wr0 + tanh_fast(t1) * wr1;

            sc += __shfl_xor_sync(0xffffffffu, sc, 1);
            sc += __shfl_xor_sync(0xffffffffu, sc, 2);
            sc += __shfl_xor_sync(0xffffffffu, sc, 4);
            float mx = sc;
            mx = fmaxf(mx, __shfl_xor_sync(0xffffffffu, mx, 8));
            mx = fmaxf(mx, __shfl_xor_sync(0xffffffffu, mx, 16));
            float ex = __expf(sc - mx);
            float ssum = ex;
            ssum += __shfl_xor_sync(0xffffffffu, ssum, 8);
            ssum += __shfl_xor_sync(0xffffffffu, ssum, 16);
            float att = __fdividef(ex, ssum);
            float av0 = __shfl_sync(0xffffffffu, att, 0);
            float av1 = __shfl_sync(0xffffffffu, att, 8);
            float av2 = __shfl_sync(0xffffffffu, att, 16);
            float av3 = __shfl_sync(0xffffffffu, att, 24);

            float vv = fmaf(av0, ur_s[0 * 33 + lane],
                       fmaf(av1, ur_s[1 * 33 + lane],
                       fmaf(av2, ur_s[2 * 33 + lane],
                            av3 * ur_s[3 * 33 + lane])));

            // q[row][r*32+lane] = tf32(ea[r]*vv)
            q_s[row * QPAD +      lane] = tf32r(ea.x * vv);
            q_s[row * QPAD + 32 + lane] = tf32r(ea.y * vv);
            q_s[row * QPAD + 64 + lane] = tf32r(ea.z * vv);
            q_s[row * QPAD + 96 + lane] = tf32r(ea.w * vv);
            __syncwarp();
        }
    }
    __syncthreads();

    // --- NOW load M tile (tf32-rounded) into the union region (over scratch) --
    for (int i = tid; i < D_ * D_; i += THREADS) {        // i = k*128 + d
        int k = i >> 7, d = i & 127;
        smem[SM_UNION + k * MPAD + d] = tf32r(__ldg(Mt + i));
    }
    __syncthreads();

    // ================= Phase 2: D[192x128] = q @ M via tf32 mma.sync ==========
    {
        const int rt = warp % 12;          // 12 row-tiles x 16 rows = 192
        const int h  = warp / 12;          // 2 d-halves x 64 cols
        const int gid = lane >> 2, tig = lane & 3;
        const float* Ms = smem + SM_UNION;

        float c[8][4];
        #pragma unroll
        for (int nt = 0; nt < 8; ++nt)
            c[nt][0] = c[nt][1] = c[nt][2] = c[nt][3] = 0.f;

        #pragma unroll 1
        for (int ks = 0; ks < 16; ++ks) {
            const int k0 = ks * 8;
            const int ar0 = (rt * 16 + gid) * QPAD + k0 + tig;
            const int ar1 = ar0 + 8 * QPAD;
            float a0 = q_s[ar0], a1 = q_s[ar1];
            float a2 = q_s[ar0 + 4], a3 = q_s[ar1 + 4];
            #pragma unroll
            for (int nt = 0; nt < 8; ++nt) {
                const int n0 = h * 64 + nt * 8 + gid;
                float b0 = Ms[(k0 + tig) * MPAD + n0];
                float b1 = Ms[(k0 + tig + 4) * MPAD + n0];
                MMA_TF32(c[nt][0], c[nt][1], c[nt][2], c[nt][3],
                         a0, a1, a2, a3, b0, b1);
            }
        }
        __syncthreads();   // all warps done reading q tile

        // fragments -> epilogue buffer (reuse q tile)
        float* epi = smem + SM_Q;
        #pragma unroll
        for (int nt = 0; nt < 8; ++nt) {
            const int col = h * 64 + nt * 8 + 2 * tig;
            const int row0 = rt * 16 + gid;
            *(float2*)(epi + row0 * QPAD + col)       = make_float2(c[nt][0], c[nt][1]);
            *(float2*)(epi + (row0 + 8) * QPAD + col) = make_float2(c[nt][2], c[nt][3]);
        }
    }
    __syncthreads();

    // ================= Epilogue: + emb gather, l2-normalize, store ============
    // row < 96: side 0 (es = e0+row); row >= 96: side 1 (es = E + e0 + row-96)
    {
        const float* epi = smem + SM_Q;
        long ess[8];
        int ents[8];
        #pragma unroll
        for (int i = 0; i < 8; ++i) {
            int row = warp * 8 + i;
            int side = row / EDGES_PB;          // uniform per warp (96 = 12*8)
            int er = e0 + row - side * EDGES_PB;
            long es = (long)side * E_ + er;
            ess[i] = (er < E_) ? es : -1;
            ents[i] = (er < E_) ? __ldg(edge_index + es) : 0;
        }
        #pragma unroll 1
        for (int i = 0; i < 8; ++i) {
            const int row = warp * 8 + i;
            float4 bv = __ldcs(&((const float4*)emb)[(long)ents[i] * 32 + lane]);
            float4 cv = *(const float4*)(epi + row * QPAD + lane * 4);
            float v0 = cv.x + bv.x, v1 = cv.y + bv.y;
            float v2 = cv.z + bv.z, v3 = cv.w + bv.w;
            float ss = v0 * v0 + v1 * v1 + v2 * v2 + v3 * v3;
            ss += __shfl_xor_sync(0xffffffffu, ss, 1);
            ss += __shfl_xor_sync(0xffffffffu, ss, 2);
            ss += __shfl_xor_sync(0xffffffffu, ss, 4);
            ss += __shfl_xor_sync(0xffffffffu, ss, 8);
            ss += __shfl_xor_sync(0xffffffffu, ss, 16);
            float inv = 1.0f / fmaxf(sqrtf(ss), 1e-12f);
            float4 o = make_float4(v0 * inv, v1 * inv, v2 * inv, v3 * inv);
            if (ess[i] >= 0)
                __stcs(&((float4*)out)[ess[i] * 32 + lane], o);  // evict-first
        }
    }
}

extern "C" void kernel_launch(void* const* d_in, const int* in_sizes, int n_in,
                              void* d_out, int out_size)
{
    (void)in_sizes; (void)n_in; (void)out_size;
    const int*   edge_index = (const int*)d_in[0];
    const float* edge_attr  = (const float*)d_in[1];
    const int*   nidx       = (const int*)d_in[2];
    const float* emb        = (const float*)d_in[3];
    const float* utab       = (const float*)d_in[4];
    const float* Wt         = (const float*)d_in[5];
    const float* wv         = (const float*)d_in[6];
    const float* Mt         = (const float*)d_in[7];
    float* out = (float*)d_out;

    conv_u_kernel<<<CONV_BLOCKS, 512>>>(utab);

    cudaFuncSetAttribute(gatne_kernel,
                         cudaFuncAttributeMaxDynamicSharedMemorySize, SMEM_BYTES);
    gatne_kernel<<<NBLOCKS, THREADS, SMEM_BYTES>>>(
        edge_index, edge_attr, nidx, emb, Wt, wv, Mt, out);
}

// round 16
// speedup vs baseline: 1.1306x; 1.0552x over previous
#include <cuda_runtime.h>
#include <cuda_bf16.h>
#include <math.h>
#include <stdint.h>

// Problem constants (GraphEmbedderGATNE): N=200000, R=4, D=128, U=32, A=16, E=131072, K=10
#define N_ENT 200000
#define R_ 4
#define D_ 128
#define U_ 32
#define A_ 16
#define E_ 131072
#define K_ 10
#define ES_TOTAL (2 * E_)                 // 262144 edge-sides
#define WPB 24                            // warps per block
#define THREADS (WPB * 32)                // 768
#define TILE 192                          // rows per block = 96 edges x 2 sides
#define EDGES_PB (TILE / 2)               // 96 edges per block
#define NBLOCKS ((E_ + EDGES_PB - 1) / EDGES_PB)   // 1366

#define QPAD 132                          // q tile row stride (conflict-free A frags)
#define MPAD 136                          // M tile row stride (conflict-free B frags)

// Shared-memory layout (float offsets).
// Phase 1 uses: W4 | w | Q | UNION(per-warp scratch)
// Phase 2 uses: W4 | w | Q | UNION(M tile)   <- M loaded AFTER phase 1
#define SM_W 0                            // W repacked: [(a*32+u)*4 + r] float4-by-r, 2048
#define SM_w 2048                         // w: [r*16 + a], 64
#define SM_Q 2112                         // q tile [row*132 + k], 25344 (reused as epilogue)
#define SM_UNION (SM_Q + TILE * QPAD)     // 27456
#define UR_OFF 0                          // ur: [r*36 + u] (float4-aligned, conflict-free), 144
#define WR_OFF 144                        // wr: [u*18 + a], 576
#define WARP_SCR 720                      // 24*720 = 17280 <= 17408 (M tile)
#define SMEM_FLOATS (SM_UNION + D_ * MPAD)        // 44864
#define SMEM_BYTES (SMEM_FLOATS * 4)              // 179456 bytes

// bf16 copy of u table: [N][128] bf16 = 51.2 MB -> fully L2-resident
__device__ __nv_bfloat16 g_ub[(size_t)N_ENT * D_];

__device__ __forceinline__ float tanh_fast(float x) {
    float y;
    asm("tanh.approx.f32 %0, %1;" : "=f"(y) : "f"(x));
    return y;
}

__device__ __forceinline__ float tf32r(float x) {
    uint32_t y;
    asm("cvt.rna.tf32.f32 %0, %1;" : "=r"(y) : "f"(x));
    return __uint_as_float(y);
}

__device__ __forceinline__ float4 add4(float4 a, float4 b) {
    return make_float4(a.x + b.x, a.y + b.y, a.z + b.z, a.w + b.w);
}

// unpack uint2 (4 bf16) -> float4
__device__ __forceinline__ float4 ub2f4(uint2 raw) {
    __nv_bfloat162 lo = *(__nv_bfloat162*)&raw.x;
    __nv_bfloat162 hi = *(__nv_bfloat162*)&raw.y;
    float2 f01 = __bfloat1622float2(lo);
    float2 f23 = __bfloat1622float2(hi);
    return make_float4(f01.x, f01.y, f23.x, f23.y);
}

#define MMA_TF32(c0, c1, c2, c3, a0, a1, a2, a3, b0, b1)                      \
    asm volatile("mma.sync.aligned.m16n8k8.row.col.f32.tf32.tf32.f32 "        \
                 "{%0,%1,%2,%3}, {%4,%5,%6,%7}, {%8,%9}, {%0,%1,%2,%3};"      \
                 : "+f"(c0), "+f"(c1), "+f"(c2), "+f"(c3)                     \
                 : "r"(__float_as_uint(a0)), "r"(__float_as_uint(a1)),        \
                   "r"(__float_as_uint(a2)), "r"(__float_as_uint(a3)),        \
                   "r"(__float_as_uint(b0)), "r"(__float_as_uint(b1)))

// ------------- conversion kernel: u (fp32) -> g_ub (bf16), streaming --------
__global__ void __launch_bounds__(512)
conv_u_kernel(const float* __restrict__ u)
{
    size_t i = (size_t)blockIdx.x * 512 + threadIdx.x;   // one uint4 (8 elems) each
    if (i < (size_t)N_ENT * D_ / 8) {
        float4 v0 = ((const float4*)u)[2 * i];
        float4 v1 = ((const float4*)u)[2 * i + 1];
        __nv_bfloat162 p0 = __floats2bfloat162_rn(v0.x, v0.y);
        __nv_bfloat162 p1 = __floats2bfloat162_rn(v0.z, v0.w);
        __nv_bfloat162 p2 = __floats2bfloat162_rn(v1.x, v1.y);
        __nv_bfloat162 p3 = __floats2bfloat162_rn(v1.z, v1.w);
        uint4 o;
        o.x = *(uint32_t*)&p0; o.y = *(uint32_t*)&p1;
        o.z = *(uint32_t*)&p2; o.w = *(uint32_t*)&p3;
        ((uint4*)g_ub)[i] = o;
    }
}
#define CONV_BLOCKS ((N_ENT * D_ / 8 + 511) / 512)   // 6250

__global__ void __launch_bounds__(THREADS, 1)
gatne_kernel(const int* __restrict__ edge_index,    // [2, E]
             const float* __restrict__ edge_attr,   // [E, R]
             const int* __restrict__ nidx,          // [2, E, K]
             const float* __restrict__ emb,         // [N, D]
             const float* __restrict__ Wt,          // [R, U, A]
             const float* __restrict__ wv,          // [R, A]
             const float* __restrict__ Mt,          // [R, U, D]
             float* __restrict__ out)               // [2, E, D]
{
    extern __shared__ float smem[];
    const int tid = threadIdx.x;

    // --- cooperative loads: W repacked by-r into float4 (M tile deferred) ---
    for (int i = tid; i < R_ * U_ * A_; i += THREADS) {
        int r = i >> 9, rem = i & 511, uu = rem >> 4, a = rem & 15;
        smem[SM_W + (a * 32 + uu) * 4 + r] = Wt[i];
    }
    if (tid < R_ * A_) smem[SM_w + tid] = wv[tid];
    __syncthreads();

    const int warp = tid >> 5, lane = tid & 31;
    float* q_s  = smem + SM_Q;
    float* ur_s = smem + SM_UNION + warp * WARP_SCR + UR_OFF;
    float* wr_s = smem + SM_UNION + warp * WARP_SCR + WR_OFF;
    const float4* W_s4 = (const float4*)(smem + SM_W);
    const float* w_s = smem + SM_w;

    const int e0 = blockIdx.x * EDGES_PB;
    const int rg = lane >> 3;
    const int cg = lane & 7;
    const int a0i = 2 * cg;

    // ========== Phase 1: 4 edges x 2 sides per warp, W_r shared per edge ======
    {
        const int e_base = e0 + warp * 4;
        const uint2* ub = (const uint2*)g_ub;    // row = 32 uint2 (128 bf16)
        uint2 t[10];
        // prologue: stage unit 0 (j=0, side=0)
        {
            int e = e_base; if (e >= E_) e = E_ - 1;
            int my_n = (lane < K_) ? __ldg(nidx + (long)e * K_ + lane) : 0;
            #pragma unroll
            for (int k = 0; k < K_; ++k) {
                int nbr = __shfl_sync(0xffffffffu, my_n, k);
                t[k] = __ldg(&ub[(long)nbr * 32 + lane]);
            }
        }

        float4 ea = make_float4(0.f, 0.f, 0.f, 0.f);
        float wr0 = 0.f, wr1 = 0.f;

        #pragma unroll 1
        for (int u = 0; u < 8; ++u) {
            const int j = u >> 1, side = u & 1;
            int e = e_base + j; if (e >= E_) e = E_ - 1;
            const int row = side * EDGES_PB + warp * 4 + j;

            // prefetch next unit's neighbor indices (long-latency, overlaps below)
            int my_n_next = 0;
            if (u + 1 < 8) {
                int jn = (u + 1) >> 1, sn = (u + 1) & 1;
                int en = e_base + jn; if (en >= E_) en = E_ - 1;
                long esn = (long)sn * E_ + en;
                my_n_next = (lane < K_) ? __ldg(nidx + esn * K_ + lane) : 0;
            }

            // consume staged gathers: unpack + pairwise tree sum
            float4 f0 = add4(ub2f4(t[0]), ub2f4(t[1]));
            float4 f1 = add4(ub2f4(t[2]), ub2f4(t[3]));
            float4 f2 = add4(ub2f4(t[4]), ub2f4(t[5]));
            float4 f3 = add4(ub2f4(t[6]), ub2f4(t[7]));
            float4 f4 = add4(ub2f4(t[8]), ub2f4(t[9]));
            float4 au = add4(add4(add4(f0, f1), add4(f2, f3)), f4);
            const float ik = 1.0f / (float)K_;
            au.x *= ik; au.y *= ik; au.z *= ik; au.w *= ik;

            // issue gathers for next unit NOW — overlap with the rest
            if (u + 1 < 8) {
                #pragma unroll
                for (int k = 0; k < K_; ++k) {
                    int nbr = __shfl_sync(0xffffffffu, my_n_next, k);
                    t[k] = __ldg(&ub[(long)nbr * 32 + lane]);
                }
            }

            // stash u_r to smem: [r*36 + u], one STS.128 (conflict-free per phase)
            *(float4*)(ur_s + rg * 36 + 4 * cg) = au;

            if (side == 0) {
                // per-edge work, shared by both sides
                ea = ((const float4*)edge_attr)[e];
                // W_r[u=lane][a] = ea . W4[a][lane]  (one LDS.128 per a)
                #pragma unroll
                for (int a2 = 0; a2 < 8; ++a2) {
                    int a = 2 * a2;
                    float4 wA = W_s4[a * 32 + lane];
                    float4 wB = W_s4[(a + 1) * 32 + lane];
                    float g0 = fmaf(ea.x, wA.x, fmaf(ea.y, wA.y,
                               fmaf(ea.z, wA.z, ea.w * wA.w)));
                    float g1 = fmaf(ea.x, wB.x, fmaf(ea.y, wB.y,
                               fmaf(ea.z, wB.z, ea.w * wB.w)));
                    ((float2*)(wr_s + lane * 18))[a2] = make_float2(g0, g1);
                }
                // w_r[a] = ea . w[:, a]
                wr0 = fmaf(ea.x, w_s[a0i], fmaf(ea.y, w_s[16 + a0i],
                      fmaf(ea.z, w_s[32 + a0i], ea.w * w_s[48 + a0i])));
                wr1 = fmaf(ea.x, w_s[a0i + 1], fmaf(ea.y, w_s[16 + a0i + 1],
                      fmaf(ea.z, w_s[32 + a0i + 1], ea.w * w_s[48 + a0i + 1])));
            }
            __syncwarp();

            // t[r=rg][a0], t[r=rg][a0+1] = sum_u u_r[r][u] * W_r[u][a]
            // ur read as float4 (broadcast within group, conflict-free across)
            float t0 = 0.f, t1 = 0.f;
            #pragma unroll
            for (int u4 = 0; u4 < 8; ++u4) {
                float4 ur4 = *(const float4*)(ur_s + rg * 36 + 4 * u4);
                float2 wa = *(const float2*)(wr_s + (4 * u4 + 0) * 18 + a0i);
                float2 wb = *(const float2*)(wr_s + (4 * u4 + 1) * 18 + a0i);
                float2 wc = *(const float2*)(wr_s + (4 * u4 + 2) * 18 + a0i);
                float2 wd = *(const float2*)(wr_s + (4 * u4 + 3) * 18 + a0i);
                t0 = fmaf(ur4.x, wa.x, fmaf(ur4.y, wb.x,
                     fmaf(ur4.z, wc.x, fmaf(ur4.w, wd.x, t0))));
                t1 = fmaf(ur4.x, wa.y, fmaf(ur4.y, wb.y,
                     fmaf(ur4.z, wc.y, fmaf(ur4.w, wd.y, t1))));
            }
            float sc = tanh_fast(t0) * wr0 + tanh_fast(t1) * wr1;

            // reduce within 8-lane r-group
            sc += __shfl_xor_sync(0xffffffffu, sc, 1);
            sc += __shfl_xor_sync(0xffffffffu, sc, 2);
            sc += __shfl_xor_sync(0xffffffffu, sc, 4);
            // gather all 4 group scores into every lane; local softmax
            // (no max-subtraction: |sc| <= ~3, exp cannot overflow; softmax is
            //  shift-invariant so the result matches to fp rounding)
            float s0 = __shfl_sync(0xffffffffu, sc, 0 * 8 + cg);
            float s1 = __shfl_sync(0xffffffffu, sc, 1 * 8 + cg);
            float s2 = __shfl_sync(0xffffffffu, sc, 2 * 8 + cg);
            float s3 = __shfl_sync(0xffffffffu, sc, 3 * 8 + cg);
            float e0x = __expf(s0), e1x = __expf(s1);
            float e2x = __expf(s2), e3x = __expf(s3);
            float esum = (e0x + e1x) + (e2x + e3x);

            // v[u=lane] = (sum_r e_r * u_r[r][lane]) / esum
            float vv = fmaf(e0x, ur_s[0 * 36 + lane],
                       fmaf(e1x, ur_s[1 * 36 + lane],
                       fmaf(e2x, ur_s[2 * 36 + lane],
                            e3x * ur_s[3 * 36 + lane])));
            vv = __fdividef(vv, esum);

            // q[row][r*32+lane] = tf32(ea[r]*vv)
            q_s[row * QPAD +      lane] = tf32r(ea.x * vv);
            q_s[row * QPAD + 32 + lane] = tf32r(ea.y * vv);
            q_s[row * QPAD + 64 + lane] = tf32r(ea.z * vv);
            q_s[row * QPAD + 96 + lane] = tf32r(ea.w * vv);
            __syncwarp();
        }
    }
    __syncthreads();

    // --- NOW load M tile (tf32-rounded) into the union region (over scratch) --
    for (int i = tid; i < D_ * D_; i += THREADS) {        // i = k*128 + d
        int k = i >> 7, d = i & 127;
        smem[SM_UNION + k * MPAD + d] = tf32r(__ldg(Mt + i));
    }
    __syncthreads();

    // ================= Phase 2: D[192x128] = q @ M via tf32 mma.sync ==========
    {
        const int rt = warp % 12;          // 12 row-tiles x 16 rows = 192
        const int h  = warp / 12;          // 2 d-halves x 64 cols
        const int gid = lane >> 2, tig = lane & 3;
        const float* Ms = smem + SM_UNION;

        float c[8][4];
        #pragma unroll
        for (int nt = 0; nt < 8; ++nt)
            c[nt][0] = c[nt][1] = c[nt][2] = c[nt][3] = 0.f;

        #pragma unroll 1
        for (int ks = 0; ks < 16; ++ks) {
            const int k0 = ks * 8;
            const int ar0 = (rt * 16 + gid) * QPAD + k0 + tig;
            const int ar1 = ar0 + 8 * QPAD;
            float a0 = q_s[ar0], a1 = q_s[ar1];
            float a2 = q_s[ar0 + 4], a3 = q_s[ar1 + 4];
            #pragma unroll
            for (int nt = 0; nt < 8; ++nt) {
                const int n0 = h * 64 + nt * 8 + gid;
                float b0 = Ms[(k0 + tig) * MPAD + n0];
                float b1 = Ms[(k0 + tig + 4) * MPAD + n0];
                MMA_TF32(c[nt][0], c[nt][1], c[nt][2], c[nt][3],
                         a0, a1, a2, a3, b0, b1);
            }
        }
        __syncthreads();   // all warps done reading q tile

        // fragments -> epilogue buffer (reuse q tile)
        float* epi = smem + SM_Q;
        #pragma unroll
        for (int nt = 0; nt < 8; ++nt) {
            const int col = h * 64 + nt * 8 + 2 * tig;
            const int row0 = rt * 16 + gid;
            *(float2*)(epi + row0 * QPAD + col)       = make_float2(c[nt][0], c[nt][1]);
            *(float2*)(epi + (row0 + 8) * QPAD + col) = make_float2(c[nt][2], c[nt][3]);
        }
    }
    __syncthreads();

    // ================= Epilogue: + emb gather, l2-normalize, store ============
    // row < 96: side 0 (es = e0+row); row >= 96: side 1 (es = E + e0 + row-96)
    {
        const float* epi = smem + SM_Q;
        long ess[8];
        int ents[8];
        #pragma unroll
        for (int i = 0; i < 8; ++i) {
            int row = warp * 8 + i;
            int side = row / EDGES_PB;          // uniform per warp (96 = 12*8)
            int er = e0 + row - side * EDGES_PB;
            long es = (long)side * E_ + er;
            ess[i] = (er < E_) ? es : -1;
            ents[i] = (er < E_) ? __ldg(edge_index + es) : 0;
        }
        #pragma unroll 1
        for (int i = 0; i < 8; ++i) {
            const int row = warp * 8 + i;
            float4 bv = __ldcs(&((const float4*)emb)[(long)ents[i] * 32 + lane]);
            float4 cv = *(const float4*)(epi + row * QPAD + lane * 4);
            float v0 = cv.x + bv.x, v1 = cv.y + bv.y;
            float v2 = cv.z + bv.z, v3 = cv.w + bv.w;
            float ss = v0 * v0 + v1 * v1 + v2 * v2 + v3 * v3;
            ss += __shfl_xor_sync(0xffffffffu, ss, 1);
            ss += __shfl_xor_sync(0xffffffffu, ss, 2);
            ss += __shfl_xor_sync(0xffffffffu, ss, 4);
            ss += __shfl_xor_sync(0xffffffffu, ss, 8);
            ss += __shfl_xor_sync(0xffffffffu, ss, 16);
            float inv = 1.0f / fmaxf(sqrtf(ss), 1e-12f);
            float4 o = make_float4(v0 * inv, v1 * inv, v2 * inv, v3 * inv);
            if (ess[i] >= 0)
                __stcs(&((float4*)out)[ess[i] * 32 + lane], o);  // evict-first
        }
    }
}

extern "C" void kernel_launch(void* const* d_in, const int* in_sizes, int n_in,
                              void* d_out, int out_size)
{
    (void)in_sizes; (void)n_in; (void)out_size;
    const int*   edge_index = (const int*)d_in[0];
    const float* edge_attr  = (const float*)d_in[1];
    const int*   nidx       = (const int*)d_in[2];
    const float* emb        = (const float*)d_in[3];
    const float* utab       = (const float*)d_in[4];
    const float* Wt         = (const float*)d_in[5];
    const float* wv         = (const float*)d_in[6];
    const float* Mt         = (const float*)d_in[7];
    float* out = (float*)d_out;

    conv_u_kernel<<<CONV_BLOCKS, 512>>>(utab);

    cudaFuncSetAttribute(gatne_kernel,
                         cudaFuncAttributeMaxDynamicSharedMemorySize, SMEM_BYTES);
    gatne_kernel<<<NBLOCKS, THREADS, SMEM_BYTES>>>(
        edge_index, edge_attr, nidx, emb, Wt, wv, Mt, out);
}